// round 9
// baseline (speedup 1.0000x reference)
#include <cuda_runtime.h>
#include <cstdint>

#define BB 512
#define TT 1024
#define NN 64
#define NJOBS (2 * BB)

// Bidirectional split of the CRF forward chain + LPT scheduling + fused
// combine + peeled score jobs.
//   Forward  job: q_t = diag(exp x_t) * E^T q_{t-1},  t = 1..nf
//   Backward job: r_{k-1} = E * (exp(x_k) ∘ r_k),      k = L-1..nf+1
//   Score    job: sc_b = unary + binary masked sums (gather-bound)
//   log_norm = C_f + C_b + log(q_nf · r_nf);  out = sc - log_norm
// Block = 256 threads: warps 0-3 (one per SMSP) are recurrence workers
// pulling LPT-ordered jobs from an atomic queue; warps 4-7 run the
// latency-bound score jobs (static assignment) and exit. The third
// arrival on g_done[b] performs the combine in-place.

__device__ float          g_qf[BB][NN];
__device__ float          g_rb[BB][NN];
__device__ float          g_cf[BB];
__device__ float          g_cb[BB];
__device__ float          g_sc[BB];
__device__ unsigned       g_ctr;
__device__ unsigned       g_done[BB];
__device__ unsigned short g_order[NJOBS];

// ---- init: reset counters, rank jobs by length descending --------------
__global__ __launch_bounds__(NJOBS) void crf_init_kernel(
    const int* __restrict__ lens)
{
    __shared__ unsigned hist[513];
    __shared__ unsigned ofs[513];
    __shared__ unsigned scan[NJOBS];
    const int tid = threadIdx.x;

    if (tid == 0) g_ctr = 0u;
    if (tid < BB) g_done[tid] = 0u;
    if (tid < 513) { hist[tid] = 0u; ofs[tid] = 0u; }
    __syncthreads();

    const int b   = tid >> 1;
    const int dir = tid & 1;
    const int L   = lens[b];
    const int nf  = (L - 1) >> 1;
    const int len = dir ? (L - 1 - nf) : nf;   // 0..512
    atomicAdd(&hist[len], 1u);
    __syncthreads();

    scan[tid] = (tid <= 512) ? hist[512 - tid] : 0u;
    __syncthreads();
#pragma unroll
    for (int off = 1; off < NJOBS; off <<= 1) {
        unsigned v = (tid >= off) ? scan[tid - off] : 0u;
        __syncthreads();
        scan[tid] += v;
        __syncthreads();
    }

    const unsigned k     = (unsigned)(512 - len);
    const unsigned start = k ? scan[k - 1] : 0u;
    const unsigned pos   = start + atomicAdd(&ofs[len], 1u);
    g_order[pos] = (unsigned short)tid;
}

#define LOAD_CHUNK(dst, base)                                                 \
    do {                                                                      \
        asm volatile("ld.shared.v2.u64 {%0,%1}, [%2];"                        \
                     : "=l"(dst[0]), "=l"(dst[1]) : "r"(base));               \
        asm volatile("ld.shared.v2.u64 {%0,%1}, [%2];"                        \
                     : "=l"(dst[2]), "=l"(dst[3]) : "r"((base) + 16));        \
        asm volatile("ld.shared.v2.u64 {%0,%1}, [%2];"                        \
                     : "=l"(dst[4]), "=l"(dst[5]) : "r"((base) + 32));        \
        asm volatile("ld.shared.v2.u64 {%0,%1}, [%2];"                        \
                     : "=l"(dst[6]), "=l"(dst[7]) : "r"((base) + 48));        \
    } while (0)

#define FMA_CHUNK(g, vv)                                                      \
    do {                                                                      \
        _Pragma("unroll")                                                     \
        for (int k = 0; k < 8; k += 4) {                                      \
            asm("fma.rn.f32x2 %0, %1, %2, %0;" : "+l"(a0) : "l"(Ea[8*(g)+k])   , "l"(vv[k]));   \
            asm("fma.rn.f32x2 %0, %1, %2, %0;" : "+l"(b0) : "l"(Eb[8*(g)+k])   , "l"(vv[k]));   \
            asm("fma.rn.f32x2 %0, %1, %2, %0;" : "+l"(a1) : "l"(Ea[8*(g)+k+1]) , "l"(vv[k+1])); \
            asm("fma.rn.f32x2 %0, %1, %2, %0;" : "+l"(b1) : "l"(Eb[8*(g)+k+1]) , "l"(vv[k+1])); \
            asm("fma.rn.f32x2 %0, %1, %2, %0;" : "+l"(a2) : "l"(Ea[8*(g)+k+2]) , "l"(vv[k+2])); \
            asm("fma.rn.f32x2 %0, %1, %2, %0;" : "+l"(b2) : "l"(Eb[8*(g)+k+2]) , "l"(vv[k+2])); \
            asm("fma.rn.f32x2 %0, %1, %2, %0;" : "+l"(a3) : "l"(Ea[8*(g)+k+3]) , "l"(vv[k+3])); \
            asm("fma.rn.f32x2 %0, %1, %2, %0;" : "+l"(b3) : "l"(Eb[8*(g)+k+3]) , "l"(vv[k+3])); \
        }                                                                     \
    } while (0)

#define MATVEC(sbase)                                                         \
    unsigned long long v0[8], v1[8];                                          \
    LOAD_CHUNK(v0, sbase);                                                    \
    LOAD_CHUNK(v1, (sbase) + 64);                                             \
    unsigned q0bits;                                                          \
    asm("mov.b64 {%0,_}, %1;" : "=r"(q0bits) : "l"(v0[0]));                   \
    const int e = (int)((q0bits >> 23) & 0xff) - 127;                         \
    const float scale = __uint_as_float((unsigned)(127 - e) << 23);           \
    unsigned long long a0 = 0ull, a1 = 0ull, a2 = 0ull, a3 = 0ull;            \
    unsigned long long b0 = 0ull, b1 = 0ull, b2 = 0ull, b3 = 0ull;            \
    FMA_CHUNK(0, v0);                                                         \
    LOAD_CHUNK(v0, (sbase) + 128);                                            \
    FMA_CHUNK(1, v1);                                                         \
    LOAD_CHUNK(v1, (sbase) + 192);                                            \
    FMA_CHUNK(2, v0);                                                         \
    FMA_CHUNK(3, v1);                                                         \
    asm("add.rn.f32x2 %0, %0, %1;" : "+l"(a0) : "l"(a1));                     \
    asm("add.rn.f32x2 %0, %0, %1;" : "+l"(a2) : "l"(a3));                     \
    asm("add.rn.f32x2 %0, %0, %1;" : "+l"(b0) : "l"(b1));                     \
    asm("add.rn.f32x2 %0, %0, %1;" : "+l"(b2) : "l"(b3));                     \
    asm("add.rn.f32x2 %0, %0, %1;" : "+l"(a0) : "l"(a2));                     \
    asm("add.rn.f32x2 %0, %0, %1;" : "+l"(b0) : "l"(b2));                     \
    float gal, gah, gbl, gbh;                                                 \
    asm("mov.b64 {%0,%1}, %2;" : "=f"(gal), "=f"(gah) : "l"(a0));             \
    asm("mov.b64 {%0,%1}, %2;" : "=f"(gbl), "=f"(gbh) : "l"(b0));

#define STS32(addr, val)                                                      \
    asm volatile("st.shared.b32 [%0], %1;" :: "r"(addr), "f"(val) : "memory")

__device__ __forceinline__ void crf_combine(int b, int lane,
                                            float* __restrict__ out)
{
    const float d0 = __ldcg(&g_qf[b][lane])      * __ldcg(&g_rb[b][lane]);
    const float d1 = __ldcg(&g_qf[b][lane + 32]) * __ldcg(&g_rb[b][lane + 32]);
    float d = d0 + d1;
#pragma unroll
    for (int o = 16; o; o >>= 1) d += __shfl_xor_sync(0xffffffffu, d, o);
    if (lane == 0) {
        const float log_norm = __ldcg(&g_cf[b]) + __ldcg(&g_cb[b]) + __logf(d);
        out[b] = __ldcg(&g_sc[b]) - log_norm;
    }
}

// arrive on g_done[b]; third arrival performs the combine
__device__ __forceinline__ void crf_arrive(int b, int lane,
                                           float* __restrict__ out)
{
    __threadfence();
    unsigned old = 0;
    if (lane == 0) old = atomicAdd(&g_done[b], 1u);
    old = __shfl_sync(0xffffffffu, old, 0);
    if (old == 2u) {
        __threadfence();
        crf_combine(b, lane, out);
    }
}

__global__ __launch_bounds__(256, 1) void crf_half_kernel(
    const float* __restrict__ inputs,   // [B, T, N]
    const float* __restrict__ trans,    // [N, N]
    const int*   __restrict__ tags,     // [B, T]
    const int*   __restrict__ lens,     // [B]
    float*       __restrict__ out)      // [B]
{
    const int lane = threadIdx.x & 31;
    const int wid  = threadIdx.x >> 5;

    __shared__ __align__(16) float pbuf[4][2][NN];

    if (wid >= 4) {
        // ================= SCORE WARPS (latency-bound) ===================
        const int w = blockIdx.x * 4 + (wid - 4);
        if (w < BB) {
            const int b = w;
            const int L = lens[b];
            const size_t tbase = (size_t)b * TT;

            float s0 = 0.f, s1 = 0.f, s2 = 0.f, s3 = 0.f;
            for (int t0 = lane; t0 < L; t0 += 128) {
                const int t1 = t0 + 32, t2 = t0 + 64, t3 = t0 + 96;
                // batched tag loads (coalesced), then independent gathers
                int g0 = -1, g1 = -1, g2 = -1, g3 = -1;
                int p0 = -1, p1 = -1, p2 = -1, p3 = -1;
                g0 = tags[tbase + t0];
                if (t0 >= 1) p0 = tags[tbase + t0 - 1];
                if (t1 < L) { g1 = tags[tbase + t1]; p1 = tags[tbase + t1 - 1]; }
                if (t2 < L) { g2 = tags[tbase + t2]; p2 = tags[tbase + t2 - 1]; }
                if (t3 < L) { g3 = tags[tbase + t3]; p3 = tags[tbase + t3 - 1]; }

                s0 += inputs[(tbase + t0) * NN + g0];
                if (p0 >= 0) s0 += trans[p0 * NN + g0];
                if (g1 >= 0) {
                    s1 += inputs[(tbase + t1) * NN + g1] + trans[p1 * NN + g1];
                }
                if (g2 >= 0) {
                    s2 += inputs[(tbase + t2) * NN + g2] + trans[p2 * NN + g2];
                }
                if (g3 >= 0) {
                    s3 += inputs[(tbase + t3) * NN + g3] + trans[p3 * NN + g3];
                }
            }
            float sc = (s0 + s1) + (s2 + s3);
#pragma unroll
            for (int o = 16; o; o >>= 1)
                sc += __shfl_xor_sync(0xffffffffu, sc, o);
            if (lane == 0) g_sc[b] = sc;
            crf_arrive(b, lane, out);
        }
        return;
    }

    // ================= RECURRENCE WARPS ==================================
    for (;;) {
        unsigned j;
        if (lane == 0) j = atomicAdd(&g_ctr, 1u);
        j = __shfl_sync(0xffffffffu, j, 0);
        if (j >= NJOBS) return;
        j = g_order[j];                      // LPT order

        const int b   = (int)(j >> 1);
        const int dir = (int)(j & 1);
        const int L   = lens[b];
        const int nf  = (L - 1) >> 1;
        const size_t tbase = (size_t)b * TT;
        const float* xp = inputs + tbase * NN;

        const unsigned sw0 = (unsigned)__cvta_generic_to_shared(
            &pbuf[wid][0][0]);
        const unsigned sA0 = sw0 + (unsigned)(lane * 4);
        const unsigned sA1 = sw0 + (unsigned)((lane + 32) * 4);
        const unsigned sB0 = sA0 + NN * 4;
        const unsigned sB1 = sA1 + NN * 4;

        if (dir == 0) {
            // ---------------- FORWARD half -------------------------------
            unsigned long long Ea[NN / 2], Eb[NN / 2];
#pragma unroll
            for (int k = 0; k < NN / 2; ++k) {
                float e0 = __expf(trans[(2 * k)     * NN + lane]);
                float e1 = __expf(trans[(2 * k + 1) * NN + lane]);
                asm("mov.b64 %0, {%1,%2};" : "=l"(Ea[k]) : "f"(e0), "f"(e1));
                float f0 = __expf(trans[(2 * k)     * NN + lane + 32]);
                float f1 = __expf(trans[(2 * k + 1) * NN + lane + 32]);
                asm("mov.b64 %0, {%1,%2};" : "=l"(Eb[k]) : "f"(f0), "f"(f1));
            }

            float x0a = xp[lane];
            float x0b = xp[lane + 32];
            float M0  = __shfl_sync(0xffffffffu, x0a, 0);
            float qa  = __expf(x0a - M0);
            float qb  = __expf(x0b - M0);
            STS32(sA0, qa);
            STS32(sA1, qb);

            int Ce = 0;
            float xa1 = 0.f, xb1 = 0.f, xa2 = 0.f, xb2 = 0.f;
            float xa3 = 0.f, xb3 = 0.f;
            if (nf >= 1) { xa1 = xp[NN + lane];     xb1 = xp[NN + lane + 32]; }
            if (nf >= 2) { xa2 = xp[2 * NN + lane]; xb2 = xp[2 * NN + lane + 32]; }
            if (nf >= 3) { xa3 = xp[3 * NN + lane]; xb3 = xp[3 * NN + lane + 32]; }

            for (int t = 1; t <= nf; ++t) {
                const unsigned rd = ((t - 1) & 1) ? (sw0 + NN * 4) : sw0;

                const float sxa = __expf(xa1);
                const float sxb = __expf(xb1);
                xa1 = xa2; xb1 = xb2;
                xa2 = xa3; xb2 = xb3;
                if (t + 3 <= nf) {
                    xa3 = xp[(size_t)(t + 3) * NN + lane];
                    xb3 = xp[(size_t)(t + 3) * NN + lane + 32];
                }

                MATVEC(rd);
                Ce += e;
                qa = (gal + gah) * (sxa * scale);
                qb = (gbl + gbh) * (sxb * scale);

                if (t & 1) { STS32(sB0, qa); STS32(sB1, qb); }
                else       { STS32(sA0, qa); STS32(sA1, qb); }
            }

            g_qf[b][lane]      = qa;
            g_qf[b][lane + 32] = qb;
            if (lane == 0)
                g_cf[b] = M0 + (float)Ce * 0.6931471805599453f;
        } else {
            // ---------------- BACKWARD half ------------------------------
            unsigned long long Ea[NN / 2], Eb[NN / 2];
#pragma unroll
            for (int k = 0; k < NN / 2; ++k) {
                float e0 = __expf(trans[lane * NN + 2 * k]);
                float e1 = __expf(trans[lane * NN + 2 * k + 1]);
                asm("mov.b64 %0, {%1,%2};" : "=l"(Ea[k]) : "f"(e0), "f"(e1));
                float f0 = __expf(trans[(lane + 32) * NN + 2 * k]);
                float f1 = __expf(trans[(lane + 32) * NN + 2 * k + 1]);
                asm("mov.b64 %0, {%1,%2};" : "=l"(Eb[k]) : "f"(f0), "f"(f1));
            }

            const int nb = (L - 1) - nf;
            float ra = 1.f, rb = 1.f;
            int Ce = 0;

            float xa1 = 0.f, xb1 = 0.f, xa2 = 0.f, xb2 = 0.f;
            float xa3 = 0.f, xb3 = 0.f;
            if (nb >= 1) {
                xa1 = xp[(size_t)(L - 1) * NN + lane];
                xb1 = xp[(size_t)(L - 1) * NN + lane + 32];
            }
            if (nb >= 2) {
                xa2 = xp[(size_t)(L - 2) * NN + lane];
                xb2 = xp[(size_t)(L - 2) * NN + lane + 32];
            }
            if (nb >= 3) {
                xa3 = xp[(size_t)(L - 3) * NN + lane];
                xb3 = xp[(size_t)(L - 3) * NN + lane + 32];
            }

            for (int s = 0; s < nb; ++s) {
                const float ua = __expf(xa1) * ra;
                const float ub = __expf(xb1) * rb;
                xa1 = xa2; xb1 = xb2;
                xa2 = xa3; xb2 = xb3;
                if (s + 3 < nb) {
                    const size_t k3 = (size_t)(L - 1 - (s + 3));
                    xa3 = xp[k3 * NN + lane];
                    xb3 = xp[k3 * NN + lane + 32];
                }

                unsigned rd;
                if (s & 1) { STS32(sB0, ua); STS32(sB1, ub); rd = sw0 + NN * 4; }
                else       { STS32(sA0, ua); STS32(sA1, ub); rd = sw0; }

                MATVEC(rd);
                Ce += e;
                ra = (gal + gah) * scale;
                rb = (gbl + gbh) * scale;
            }

            g_rb[b][lane]      = ra;
            g_rb[b][lane + 32] = rb;
            if (lane == 0)
                g_cb[b] = (float)Ce * 0.6931471805599453f;
        }

        crf_arrive(b, lane, out);
    }
}

extern "C" void kernel_launch(void* const* d_in, const int* in_sizes, int n_in,
                              void* d_out, int out_size)
{
    const float* inputs = (const float*)d_in[0];
    const float* trans  = (const float*)d_in[1];
    const int*   tags   = (const int*)d_in[2];
    const int*   lens   = (const int*)d_in[3];
    float*       out    = (float*)d_out;

    crf_init_kernel<<<1, NJOBS>>>(lens);
    crf_half_kernel<<<148, 256>>>(inputs, trans, tags, lens, out);
}

// round 10
// speedup vs baseline: 1.2076x; 1.2076x over previous
#include <cuda_runtime.h>
#include <cstdint>

#define BB 512
#define TT 1024
#define NN 64
#define NJOBS (2 * BB)

// Bidirectional split of the CRF forward chain + LPT scheduling + fused
// combine (R8 structure) + MLP-batched score gather.
//   Forward  job: q_t = diag(exp x_t) * E^T q_{t-1},  t = 1..nf  (+ scores)
//   Backward job: r_{k-1} = E * (exp(x_k) ∘ r_k),      k = L-1..nf+1
//   log_norm = C_f + C_b + log(q_nf · r_nf);  out = sc - log_norm
// Persistent kernel: 148 blocks x 4 warps (<=1 warp per SMSP chip-wide),
// LPT job order from a histogram-rank init kernel; second finisher per
// batch performs the combine in-place.

__device__ float          g_qf[BB][NN];
__device__ float          g_rb[BB][NN];
__device__ float          g_cf[BB];
__device__ float          g_cb[BB];
__device__ float          g_sc[BB];
__device__ unsigned       g_ctr;
__device__ unsigned       g_done[BB];
__device__ unsigned short g_order[NJOBS];

// ---- init: reset counters, rank jobs by length descending --------------
__global__ __launch_bounds__(NJOBS) void crf_init_kernel(
    const int* __restrict__ lens)
{
    __shared__ unsigned hist[513];
    __shared__ unsigned ofs[513];
    __shared__ unsigned scan[NJOBS];
    const int tid = threadIdx.x;

    if (tid == 0) g_ctr = 0u;
    if (tid < BB) g_done[tid] = 0u;
    if (tid < 513) { hist[tid] = 0u; ofs[tid] = 0u; }
    __syncthreads();

    const int b   = tid >> 1;
    const int dir = tid & 1;
    const int L   = lens[b];
    const int nf  = (L - 1) >> 1;
    const int len = dir ? (L - 1 - nf) : nf;   // 0..512
    atomicAdd(&hist[len], 1u);
    __syncthreads();

    scan[tid] = (tid <= 512) ? hist[512 - tid] : 0u;
    __syncthreads();
#pragma unroll
    for (int off = 1; off < NJOBS; off <<= 1) {
        unsigned v = (tid >= off) ? scan[tid - off] : 0u;
        __syncthreads();
        scan[tid] += v;
        __syncthreads();
    }

    const unsigned k     = (unsigned)(512 - len);
    const unsigned start = k ? scan[k - 1] : 0u;
    const unsigned pos   = start + atomicAdd(&ofs[len], 1u);
    g_order[pos] = (unsigned short)tid;
}

#define LOAD_CHUNK(dst, base)                                                 \
    do {                                                                      \
        asm volatile("ld.shared.v2.u64 {%0,%1}, [%2];"                        \
                     : "=l"(dst[0]), "=l"(dst[1]) : "r"(base));               \
        asm volatile("ld.shared.v2.u64 {%0,%1}, [%2];"                        \
                     : "=l"(dst[2]), "=l"(dst[3]) : "r"((base) + 16));        \
        asm volatile("ld.shared.v2.u64 {%0,%1}, [%2];"                        \
                     : "=l"(dst[4]), "=l"(dst[5]) : "r"((base) + 32));        \
        asm volatile("ld.shared.v2.u64 {%0,%1}, [%2];"                        \
                     : "=l"(dst[6]), "=l"(dst[7]) : "r"((base) + 48));        \
    } while (0)

#define FMA_CHUNK(g, vv)                                                      \
    do {                                                                      \
        _Pragma("unroll")                                                     \
        for (int k = 0; k < 8; k += 4) {                                      \
            asm("fma.rn.f32x2 %0, %1, %2, %0;" : "+l"(a0) : "l"(Ea[8*(g)+k])   , "l"(vv[k]));   \
            asm("fma.rn.f32x2 %0, %1, %2, %0;" : "+l"(b0) : "l"(Eb[8*(g)+k])   , "l"(vv[k]));   \
            asm("fma.rn.f32x2 %0, %1, %2, %0;" : "+l"(a1) : "l"(Ea[8*(g)+k+1]) , "l"(vv[k+1])); \
            asm("fma.rn.f32x2 %0, %1, %2, %0;" : "+l"(b1) : "l"(Eb[8*(g)+k+1]) , "l"(vv[k+1])); \
            asm("fma.rn.f32x2 %0, %1, %2, %0;" : "+l"(a2) : "l"(Ea[8*(g)+k+2]) , "l"(vv[k+2])); \
            asm("fma.rn.f32x2 %0, %1, %2, %0;" : "+l"(b2) : "l"(Eb[8*(g)+k+2]) , "l"(vv[k+2])); \
            asm("fma.rn.f32x2 %0, %1, %2, %0;" : "+l"(a3) : "l"(Ea[8*(g)+k+3]) , "l"(vv[k+3])); \
            asm("fma.rn.f32x2 %0, %1, %2, %0;" : "+l"(b3) : "l"(Eb[8*(g)+k+3]) , "l"(vv[k+3])); \
        }                                                                     \
    } while (0)

#define MATVEC(sbase)                                                         \
    unsigned long long v0[8], v1[8];                                          \
    LOAD_CHUNK(v0, sbase);                                                    \
    LOAD_CHUNK(v1, (sbase) + 64);                                             \
    unsigned q0bits;                                                          \
    asm("mov.b64 {%0,_}, %1;" : "=r"(q0bits) : "l"(v0[0]));                   \
    const int e = (int)((q0bits >> 23) & 0xff) - 127;                         \
    const float scale = __uint_as_float((unsigned)(127 - e) << 23);           \
    unsigned long long a0 = 0ull, a1 = 0ull, a2 = 0ull, a3 = 0ull;            \
    unsigned long long b0 = 0ull, b1 = 0ull, b2 = 0ull, b3 = 0ull;            \
    FMA_CHUNK(0, v0);                                                         \
    LOAD_CHUNK(v0, (sbase) + 128);                                            \
    FMA_CHUNK(1, v1);                                                         \
    LOAD_CHUNK(v1, (sbase) + 192);                                            \
    FMA_CHUNK(2, v0);                                                         \
    FMA_CHUNK(3, v1);                                                         \
    asm("add.rn.f32x2 %0, %0, %1;" : "+l"(a0) : "l"(a1));                     \
    asm("add.rn.f32x2 %0, %0, %1;" : "+l"(a2) : "l"(a3));                     \
    asm("add.rn.f32x2 %0, %0, %1;" : "+l"(b0) : "l"(b1));                     \
    asm("add.rn.f32x2 %0, %0, %1;" : "+l"(b2) : "l"(b3));                     \
    asm("add.rn.f32x2 %0, %0, %1;" : "+l"(a0) : "l"(a2));                     \
    asm("add.rn.f32x2 %0, %0, %1;" : "+l"(b0) : "l"(b2));                     \
    float gal, gah, gbl, gbh;                                                 \
    asm("mov.b64 {%0,%1}, %2;" : "=f"(gal), "=f"(gah) : "l"(a0));             \
    asm("mov.b64 {%0,%1}, %2;" : "=f"(gbl), "=f"(gbh) : "l"(b0));

#define STS32(addr, val)                                                      \
    asm volatile("st.shared.b32 [%0], %1;" :: "r"(addr), "f"(val) : "memory")

__device__ __forceinline__ void crf_combine(int b, int lane,
                                            float* __restrict__ out)
{
    const float d0 = __ldcg(&g_qf[b][lane])      * __ldcg(&g_rb[b][lane]);
    const float d1 = __ldcg(&g_qf[b][lane + 32]) * __ldcg(&g_rb[b][lane + 32]);
    float d = d0 + d1;
#pragma unroll
    for (int o = 16; o; o >>= 1) d += __shfl_xor_sync(0xffffffffu, d, o);
    if (lane == 0) {
        const float log_norm = __ldcg(&g_cf[b]) + __ldcg(&g_cb[b]) + __logf(d);
        out[b] = __ldcg(&g_sc[b]) - log_norm;
    }
}

__global__ __launch_bounds__(128, 1) void crf_half_kernel(
    const float* __restrict__ inputs,   // [B, T, N]
    const float* __restrict__ trans,    // [N, N]
    const int*   __restrict__ tags,     // [B, T]
    const int*   __restrict__ lens,     // [B]
    float*       __restrict__ out)      // [B]
{
    const int lane = threadIdx.x & 31;
    const int wid  = threadIdx.x >> 5;

    __shared__ __align__(16) float pbuf[4][2][NN];

    for (;;) {
        unsigned j;
        if (lane == 0) j = atomicAdd(&g_ctr, 1u);
        j = __shfl_sync(0xffffffffu, j, 0);
        if (j >= NJOBS) return;
        j = g_order[j];                      // LPT order

        const int b   = (int)(j >> 1);
        const int dir = (int)(j & 1);
        const int L   = lens[b];
        const int nf  = (L - 1) >> 1;
        const size_t tbase = (size_t)b * TT;
        const float* xp = inputs + tbase * NN;

        const unsigned sw0 = (unsigned)__cvta_generic_to_shared(
            &pbuf[wid][0][0]);
        const unsigned sA0 = sw0 + (unsigned)(lane * 4);
        const unsigned sA1 = sw0 + (unsigned)((lane + 32) * 4);
        const unsigned sB0 = sA0 + NN * 4;
        const unsigned sB1 = sA1 + NN * 4;

        if (dir == 0) {
            // ---------------- FORWARD half + scores ----------------------
            // MLP-batched score gather: rounds of 8 strided t per lane;
            // phase 1 = 16 independent tag loads, phase 2 = 16 independent
            // gathers (all in flight together).
            float sc0 = 0.f, sc1 = 0.f;
            for (int k0 = 0; k0 < 32; k0 += 8) {
                if (32 * k0 >= L) break;          // warp-uniform
                int tg[8], tp[8];
#pragma unroll
                for (int u = 0; u < 8; ++u) {
                    const int t = lane + 32 * (k0 + u);
                    tg[u] = -1; tp[u] = -1;
                    if (t < L) {
                        tg[u] = tags[tbase + t];
                        if (t >= 1) tp[u] = tags[tbase + t - 1];
                    }
                }
#pragma unroll
                for (int u = 0; u < 8; ++u) {
                    const int t = lane + 32 * (k0 + u);
                    if (tg[u] >= 0) {
                        const float uv = inputs[(tbase + t) * NN + tg[u]];
                        if (tp[u] >= 0) {
                            sc1 += trans[tp[u] * NN + tg[u]];
                        }
                        sc0 += uv;
                    }
                }
            }
            float sc = sc0 + sc1;
#pragma unroll
            for (int o = 16; o; o >>= 1)
                sc += __shfl_xor_sync(0xffffffffu, sc, o);

            unsigned long long Ea[NN / 2], Eb[NN / 2];
#pragma unroll
            for (int k = 0; k < NN / 2; ++k) {
                float e0 = __expf(trans[(2 * k)     * NN + lane]);
                float e1 = __expf(trans[(2 * k + 1) * NN + lane]);
                asm("mov.b64 %0, {%1,%2};" : "=l"(Ea[k]) : "f"(e0), "f"(e1));
                float f0 = __expf(trans[(2 * k)     * NN + lane + 32]);
                float f1 = __expf(trans[(2 * k + 1) * NN + lane + 32]);
                asm("mov.b64 %0, {%1,%2};" : "=l"(Eb[k]) : "f"(f0), "f"(f1));
            }

            float x0a = xp[lane];
            float x0b = xp[lane + 32];
            float M0  = __shfl_sync(0xffffffffu, x0a, 0);
            float qa  = __expf(x0a - M0);
            float qb  = __expf(x0b - M0);
            STS32(sA0, qa);
            STS32(sA1, qb);

            int Ce = 0;
            float xa1 = 0.f, xb1 = 0.f, xa2 = 0.f, xb2 = 0.f;
            if (nf >= 1) { xa1 = xp[NN + lane];     xb1 = xp[NN + lane + 32]; }
            if (nf >= 2) { xa2 = xp[2 * NN + lane]; xb2 = xp[2 * NN + lane + 32]; }

            for (int t = 1; t <= nf; ++t) {
                const unsigned rd = ((t - 1) & 1) ? (sw0 + NN * 4) : sw0;

                const float sxa = __expf(xa1);
                const float sxb = __expf(xb1);
                xa1 = xa2; xb1 = xb2;
                if (t + 2 <= nf) {
                    xa2 = xp[(size_t)(t + 2) * NN + lane];
                    xb2 = xp[(size_t)(t + 2) * NN + lane + 32];
                }

                MATVEC(rd);
                Ce += e;
                qa = (gal + gah) * (sxa * scale);
                qb = (gbl + gbh) * (sxb * scale);

                if (t & 1) { STS32(sB0, qa); STS32(sB1, qb); }
                else       { STS32(sA0, qa); STS32(sA1, qb); }
            }

            g_qf[b][lane]      = qa;
            g_qf[b][lane + 32] = qb;
            if (lane == 0) {
                g_cf[b] = M0 + (float)Ce * 0.6931471805599453f;
                g_sc[b] = sc;
            }
        } else {
            // ---------------- BACKWARD half ------------------------------
            unsigned long long Ea[NN / 2], Eb[NN / 2];
#pragma unroll
            for (int k = 0; k < NN / 2; ++k) {
                float e0 = __expf(trans[lane * NN + 2 * k]);
                float e1 = __expf(trans[lane * NN + 2 * k + 1]);
                asm("mov.b64 %0, {%1,%2};" : "=l"(Ea[k]) : "f"(e0), "f"(e1));
                float f0 = __expf(trans[(lane + 32) * NN + 2 * k]);
                float f1 = __expf(trans[(lane + 32) * NN + 2 * k + 1]);
                asm("mov.b64 %0, {%1,%2};" : "=l"(Eb[k]) : "f"(f0), "f"(f1));
            }

            const int nb = (L - 1) - nf;
            float ra = 1.f, rb = 1.f;
            int Ce = 0;

            float xa1 = 0.f, xb1 = 0.f, xa2 = 0.f, xb2 = 0.f;
            if (nb >= 1) {
                xa1 = xp[(size_t)(L - 1) * NN + lane];
                xb1 = xp[(size_t)(L - 1) * NN + lane + 32];
            }
            if (nb >= 2) {
                xa2 = xp[(size_t)(L - 2) * NN + lane];
                xb2 = xp[(size_t)(L - 2) * NN + lane + 32];
            }

            for (int s = 0; s < nb; ++s) {
                const float ua = __expf(xa1) * ra;
                const float ub = __expf(xb1) * rb;
                xa1 = xa2; xb1 = xb2;
                if (s + 2 < nb) {
                    const size_t k2 = (size_t)(L - 1 - (s + 2));
                    xa2 = xp[k2 * NN + lane];
                    xb2 = xp[k2 * NN + lane + 32];
                }

                unsigned rd;
                if (s & 1) { STS32(sB0, ua); STS32(sB1, ub); rd = sw0 + NN * 4; }
                else       { STS32(sA0, ua); STS32(sA1, ub); rd = sw0; }

                MATVEC(rd);
                Ce += e;
                ra = (gal + gah) * scale;
                rb = (gbl + gbh) * scale;
            }

            g_rb[b][lane]      = ra;
            g_rb[b][lane + 32] = rb;
            if (lane == 0)
                g_cb[b] = (float)Ce * 0.6931471805599453f;
        }

        // ---- completion: second finisher combines ----
        __threadfence();
        unsigned old = 0;
        if (lane == 0) old = atomicAdd(&g_done[b], 1u);
        old = __shfl_sync(0xffffffffu, old, 0);
        if (old == 1u) {
            __threadfence();
            crf_combine(b, lane, out);
        }
    }
}

extern "C" void kernel_launch(void* const* d_in, const int* in_sizes, int n_in,
                              void* d_out, int out_size)
{
    const float* inputs = (const float*)d_in[0];
    const float* trans  = (const float*)d_in[1];
    const int*   tags   = (const int*)d_in[2];
    const int*   lens   = (const int*)d_in[3];
    float*       out    = (float*)d_out;

    crf_init_kernel<<<1, NJOBS>>>(lens);
    crf_half_kernel<<<148, 128>>>(inputs, trans, tags, lens, out);
}

// round 11
// speedup vs baseline: 1.3345x; 1.1051x over previous
#include <cuda_runtime.h>
#include <cstdint>

#define BB 512
#define TT 1024
#define NN 64
#define NJOBS (2 * BB)

// Bidirectional split of the CRF forward chain + LPT scheduling + fused
// combine. R11: interleaved p layout (1 x STS.64/step), single smem buffer
// (in-order MIO, no parity), renorm every 2nd step (exact; power-of-2 scale
// + integer Ce), loop unrolled x2, x-prefetch depth 4.
//   Forward  job: q_t = diag(exp x_t) * E^T q_{t-1},  t = 1..nf  (+ scores)
//   Backward job: r_{k-1} = E * (exp(x_k) . r_k),      k = L-1..nf+1
//   log_norm = C_f + C_b + log(q_nf . r_nf);  out = sc - log_norm

__device__ float          g_qf[BB][NN];
__device__ float          g_rb[BB][NN];
__device__ float          g_cf[BB];
__device__ float          g_cb[BB];
__device__ float          g_sc[BB];
__device__ unsigned       g_ctr;
__device__ unsigned       g_done[BB];
__device__ unsigned short g_order[NJOBS];

// ---- init: reset counters, rank jobs by length descending --------------
__global__ __launch_bounds__(NJOBS) void crf_init_kernel(
    const int* __restrict__ lens)
{
    __shared__ unsigned hist[513];
    __shared__ unsigned ofs[513];
    __shared__ unsigned scan[NJOBS];
    const int tid = threadIdx.x;

    if (tid == 0) g_ctr = 0u;
    if (tid < BB) g_done[tid] = 0u;
    if (tid < 513) { hist[tid] = 0u; ofs[tid] = 0u; }
    __syncthreads();

    const int b   = tid >> 1;
    const int dir = tid & 1;
    const int L   = lens[b];
    const int nf  = (L - 1) >> 1;
    const int len = dir ? (L - 1 - nf) : nf;   // 0..512
    atomicAdd(&hist[len], 1u);
    __syncthreads();

    scan[tid] = (tid <= 512) ? hist[512 - tid] : 0u;
    __syncthreads();
#pragma unroll
    for (int off = 1; off < NJOBS; off <<= 1) {
        unsigned v = (tid >= off) ? scan[tid - off] : 0u;
        __syncthreads();
        scan[tid] += v;
        __syncthreads();
    }

    const unsigned k     = (unsigned)(512 - len);
    const unsigned start = k ? scan[k - 1] : 0u;
    const unsigned pos   = start + atomicAdd(&ofs[len], 1u);
    g_order[pos] = (unsigned short)tid;
}

#define LOAD_CHUNK(dst, base)                                                 \
    do {                                                                      \
        asm volatile("ld.shared.v2.u64 {%0,%1}, [%2];"                        \
                     : "=l"(dst[0]), "=l"(dst[1]) : "r"(base));               \
        asm volatile("ld.shared.v2.u64 {%0,%1}, [%2];"                        \
                     : "=l"(dst[2]), "=l"(dst[3]) : "r"((base) + 16));        \
        asm volatile("ld.shared.v2.u64 {%0,%1}, [%2];"                        \
                     : "=l"(dst[4]), "=l"(dst[5]) : "r"((base) + 32));        \
        asm volatile("ld.shared.v2.u64 {%0,%1}, [%2];"                        \
                     : "=l"(dst[6]), "=l"(dst[7]) : "r"((base) + 48));        \
    } while (0)

#define FMA_CHUNK(g, vv)                                                      \
    do {                                                                      \
        _Pragma("unroll")                                                     \
        for (int k = 0; k < 8; k += 4) {                                      \
            asm("fma.rn.f32x2 %0, %1, %2, %0;" : "+l"(a0) : "l"(Ea[8*(g)+k])   , "l"(vv[k]));   \
            asm("fma.rn.f32x2 %0, %1, %2, %0;" : "+l"(b0) : "l"(Eb[8*(g)+k])   , "l"(vv[k]));   \
            asm("fma.rn.f32x2 %0, %1, %2, %0;" : "+l"(a1) : "l"(Ea[8*(g)+k+1]) , "l"(vv[k+1])); \
            asm("fma.rn.f32x2 %0, %1, %2, %0;" : "+l"(b1) : "l"(Eb[8*(g)+k+1]) , "l"(vv[k+1])); \
            asm("fma.rn.f32x2 %0, %1, %2, %0;" : "+l"(a2) : "l"(Ea[8*(g)+k+2]) , "l"(vv[k+2])); \
            asm("fma.rn.f32x2 %0, %1, %2, %0;" : "+l"(b2) : "l"(Eb[8*(g)+k+2]) , "l"(vv[k+2])); \
            asm("fma.rn.f32x2 %0, %1, %2, %0;" : "+l"(a3) : "l"(Ea[8*(g)+k+3]) , "l"(vv[k+3])); \
            asm("fma.rn.f32x2 %0, %1, %2, %0;" : "+l"(b3) : "l"(Eb[8*(g)+k+3]) , "l"(vv[k+3])); \
        }                                                                     \
    } while (0)

#define MATVEC_TAIL()                                                         \
    asm("add.rn.f32x2 %0, %0, %1;" : "+l"(a0) : "l"(a1));                     \
    asm("add.rn.f32x2 %0, %0, %1;" : "+l"(a2) : "l"(a3));                     \
    asm("add.rn.f32x2 %0, %0, %1;" : "+l"(b0) : "l"(b1));                     \
    asm("add.rn.f32x2 %0, %0, %1;" : "+l"(b2) : "l"(b3));                     \
    asm("add.rn.f32x2 %0, %0, %1;" : "+l"(a0) : "l"(a2));                     \
    asm("add.rn.f32x2 %0, %0, %1;" : "+l"(b0) : "l"(b2));                     \
    asm("mov.b64 {%0,%1}, %2;" : "=f"(gal), "=f"(gah) : "l"(a0));             \
    asm("mov.b64 {%0,%1}, %2;" : "=f"(gbl), "=f"(gbh) : "l"(b0));

// no-renorm matvec: produces gal,gah,gbl,gbh
#define MATVEC_NR(sbase)                                                      \
    unsigned long long v0[8], v1[8];                                          \
    LOAD_CHUNK(v0, sbase);                                                    \
    LOAD_CHUNK(v1, (sbase) + 64);                                             \
    unsigned long long a0 = 0ull, a1 = 0ull, a2 = 0ull, a3 = 0ull;            \
    unsigned long long b0 = 0ull, b1 = 0ull, b2 = 0ull, b3 = 0ull;            \
    float gal, gah, gbl, gbh;                                                 \
    FMA_CHUNK(0, v0);                                                         \
    LOAD_CHUNK(v0, (sbase) + 128);                                            \
    FMA_CHUNK(1, v1);                                                         \
    LOAD_CHUNK(v1, (sbase) + 192);                                            \
    FMA_CHUNK(2, v0);                                                         \
    FMA_CHUNK(3, v1);                                                         \
    MATVEC_TAIL()

// renorm matvec: additionally extracts exponent of p[0], updates Ce,
// defines `scale` = 2^-e
#define MATVEC_RN(sbase)                                                      \
    unsigned long long v0[8], v1[8];                                          \
    LOAD_CHUNK(v0, sbase);                                                    \
    LOAD_CHUNK(v1, (sbase) + 64);                                             \
    unsigned q0bits;                                                          \
    asm("mov.b64 {%0,_}, %1;" : "=r"(q0bits) : "l"(v0[0]));                   \
    const int e = (int)((q0bits >> 23) & 0xff) - 127;                         \
    Ce += e;                                                                  \
    const float scale = __uint_as_float((unsigned)(127 - e) << 23);           \
    unsigned long long a0 = 0ull, a1 = 0ull, a2 = 0ull, a3 = 0ull;            \
    unsigned long long b0 = 0ull, b1 = 0ull, b2 = 0ull, b3 = 0ull;            \
    float gal, gah, gbl, gbh;                                                 \
    FMA_CHUNK(0, v0);                                                         \
    LOAD_CHUNK(v0, (sbase) + 128);                                            \
    FMA_CHUNK(1, v1);                                                         \
    LOAD_CHUNK(v1, (sbase) + 192);                                            \
    FMA_CHUNK(2, v0);                                                         \
    FMA_CHUNK(3, v1);                                                         \
    MATVEC_TAIL()

#define STS64P(addr, lo, hi)                                                  \
    do {                                                                      \
        unsigned long long _pk;                                               \
        asm("mov.b64 %0, {%1,%2};" : "=l"(_pk) : "f"(lo), "f"(hi));           \
        asm volatile("st.shared.b64 [%0], %1;" :: "r"(addr), "l"(_pk)         \
                     : "memory");                                             \
    } while (0)

__device__ __forceinline__ void crf_combine(int b, int lane,
                                            float* __restrict__ out)
{
    const float d0 = __ldcg(&g_qf[b][lane])      * __ldcg(&g_rb[b][lane]);
    const float d1 = __ldcg(&g_qf[b][lane + 32]) * __ldcg(&g_rb[b][lane + 32]);
    float d = d0 + d1;
#pragma unroll
    for (int o = 16; o; o >>= 1) d += __shfl_xor_sync(0xffffffffu, d, o);
    if (lane == 0) {
        const float log_norm = __ldcg(&g_cf[b]) + __ldcg(&g_cb[b]) + __logf(d);
        out[b] = __ldcg(&g_sc[b]) - log_norm;
    }
}

__global__ __launch_bounds__(128, 1) void crf_half_kernel(
    const float* __restrict__ inputs,   // [B, T, N]
    const float* __restrict__ trans,    // [N, N]
    const int*   __restrict__ tags,     // [B, T]
    const int*   __restrict__ lens,     // [B]
    float*       __restrict__ out)      // [B]
{
    const int lane = threadIdx.x & 31;
    const int wid  = threadIdx.x >> 5;

    __shared__ __align__(16) float pbuf[4][NN];

    for (;;) {
        unsigned j;
        if (lane == 0) j = atomicAdd(&g_ctr, 1u);
        j = __shfl_sync(0xffffffffu, j, 0);
        if (j >= NJOBS) return;
        j = g_order[j];                      // LPT order

        const int b   = (int)(j >> 1);
        const int dir = (int)(j & 1);
        const int L   = lens[b];
        const int nf  = (L - 1) >> 1;
        const size_t tbase = (size_t)b * TT;
        const float* xp = inputs + tbase * NN;

        const unsigned sw0 =
            (unsigned)__cvta_generic_to_shared(&pbuf[wid][0]);
        const unsigned sst = sw0 + (unsigned)(lane * 8);

        if (dir == 0) {
            // ---------------- FORWARD half + scores ----------------------
            float sc = 0.f;
            for (int t = lane; t < L; t += 32) {
                int tg = tags[tbase + t];
                sc += inputs[(tbase + t) * NN + tg];
                if (t >= 1) {
                    int tp = tags[tbase + t - 1];
                    sc += trans[tp * NN + tg];
                }
            }
#pragma unroll
            for (int o = 16; o; o >>= 1)
                sc += __shfl_xor_sync(0xffffffffu, sc, o);

            // E = exp(trans), interleaved row packing:
            // Ea[w] = (E[w][lane], E[w+32][lane]) matches p word w =
            // (p_w, p_{w+32}).
            unsigned long long Ea[32], Eb[32];
#pragma unroll
            for (int w = 0; w < 32; ++w) {
                float e0 = __expf(trans[w * NN + lane]);
                float e1 = __expf(trans[(w + 32) * NN + lane]);
                asm("mov.b64 %0, {%1,%2};" : "=l"(Ea[w]) : "f"(e0), "f"(e1));
                float f0 = __expf(trans[w * NN + lane + 32]);
                float f1 = __expf(trans[(w + 32) * NN + lane + 32]);
                asm("mov.b64 %0, {%1,%2};" : "=l"(Eb[w]) : "f"(f0), "f"(f1));
            }

            float x0a = xp[lane];
            float x0b = xp[lane + 32];
            float M0  = __shfl_sync(0xffffffffu, x0a, 0);
            float qa  = __expf(x0a - M0);
            float qb  = __expf(x0b - M0);
            STS64P(sst, qa, qb);

            int Ce = 0;
            float xa[4], xb[4];
#pragma unroll
            for (int u = 0; u < 4; ++u) {
                xa[u] = 0.f; xb[u] = 0.f;
                if (1 + u <= nf) {
                    xa[u] = xp[(size_t)(1 + u) * NN + lane];
                    xb[u] = xp[(size_t)(1 + u) * NN + lane + 32];
                }
            }

            int t = 1;
            for (; t + 1 <= nf; t += 2) {
                const float xAa = xa[0], xAb = xb[0];
                const float xBa = xa[1], xBb = xb[1];
                xa[0] = xa[2]; xb[0] = xb[2];
                xa[1] = xa[3]; xb[1] = xb[3];
                if (t + 4 <= nf) {
                    xa[2] = xp[(size_t)(t + 4) * NN + lane];
                    xb[2] = xp[(size_t)(t + 4) * NN + lane + 32];
                }
                if (t + 5 <= nf) {
                    xa[3] = xp[(size_t)(t + 5) * NN + lane];
                    xb[3] = xp[(size_t)(t + 5) * NN + lane + 32];
                }
                {   // step t: no renorm
                    const float sxa = __expf(xAa);
                    const float sxb = __expf(xAb);
                    MATVEC_NR(sw0);
                    qa = (gal + gah) * sxa;
                    qb = (gbl + gbh) * sxb;
                    STS64P(sst, qa, qb);
                }
                {   // step t+1: renorm
                    const float sxa = __expf(xBa);
                    const float sxb = __expf(xBb);
                    MATVEC_RN(sw0);
                    qa = (gal + gah) * (sxa * scale);
                    qb = (gbl + gbh) * (sxb * scale);
                    STS64P(sst, qa, qb);
                }
            }
            if (t <= nf) {   // tail step: renorm, no store needed
                const float sxa = __expf(xa[0]);
                const float sxb = __expf(xb[0]);
                MATVEC_RN(sw0);
                qa = (gal + gah) * (sxa * scale);
                qb = (gbl + gbh) * (sxb * scale);
            }

            g_qf[b][lane]      = qa;
            g_qf[b][lane + 32] = qb;
            if (lane == 0) {
                g_cf[b] = M0 + (float)Ce * 0.6931471805599453f;
                g_sc[b] = sc;
            }
        } else {
            // ---------------- BACKWARD half ------------------------------
            // Ea[w] = (E[lane][w], E[lane][w+32]) matches u word w.
            unsigned long long Ea[32], Eb[32];
#pragma unroll
            for (int w = 0; w < 32; ++w) {
                float e0 = __expf(trans[lane * NN + w]);
                float e1 = __expf(trans[lane * NN + w + 32]);
                asm("mov.b64 %0, {%1,%2};" : "=l"(Ea[w]) : "f"(e0), "f"(e1));
                float f0 = __expf(trans[(lane + 32) * NN + w]);
                float f1 = __expf(trans[(lane + 32) * NN + w + 32]);
                asm("mov.b64 %0, {%1,%2};" : "=l"(Eb[w]) : "f"(f0), "f"(f1));
            }

            const int nb = (L - 1) - nf;
            float ra = 1.f, rb = 1.f;
            int Ce = 0;

            float xa[4], xb[4];
#pragma unroll
            for (int u = 0; u < 4; ++u) {
                xa[u] = 0.f; xb[u] = 0.f;
                if (u < nb) {
                    xa[u] = xp[(size_t)(L - 1 - u) * NN + lane];
                    xb[u] = xp[(size_t)(L - 1 - u) * NN + lane + 32];
                }
            }

            int s = 0;
            for (; s + 1 < nb; s += 2) {
                const float xAa = xa[0], xAb = xb[0];
                const float xBa = xa[1], xBb = xb[1];
                xa[0] = xa[2]; xb[0] = xb[2];
                xa[1] = xa[3]; xb[1] = xb[3];
                if (s + 4 < nb) {
                    const size_t k4 = (size_t)(L - 1 - (s + 4));
                    xa[2] = xp[k4 * NN + lane];
                    xb[2] = xp[k4 * NN + lane + 32];
                }
                if (s + 5 < nb) {
                    const size_t k5 = (size_t)(L - 1 - (s + 5));
                    xa[3] = xp[k5 * NN + lane];
                    xb[3] = xp[k5 * NN + lane + 32];
                }
                {   // step s: no renorm
                    const float ua = __expf(xAa) * ra;
                    const float ub = __expf(xAb) * rb;
                    STS64P(sst, ua, ub);
                    MATVEC_NR(sw0);
                    ra = gal + gah;
                    rb = gbl + gbh;
                }
                {   // step s+1: renorm
                    const float ua = __expf(xBa) * ra;
                    const float ub = __expf(xBb) * rb;
                    STS64P(sst, ua, ub);
                    MATVEC_RN(sw0);
                    ra = (gal + gah) * scale;
                    rb = (gbl + gbh) * scale;
                }
            }
            if (s < nb) {   // tail step: renorm
                const float ua = __expf(xa[0]) * ra;
                const float ub = __expf(xb[0]) * rb;
                STS64P(sst, ua, ub);
                MATVEC_RN(sw0);
                ra = (gal + gah) * scale;
                rb = (gbl + gbh) * scale;
            }

            g_rb[b][lane]      = ra;
            g_rb[b][lane + 32] = rb;
            if (lane == 0)
                g_cb[b] = (float)Ce * 0.6931471805599453f;
        }

        // ---- completion: second finisher combines ----
        __threadfence();
        unsigned old = 0;
        if (lane == 0) old = atomicAdd(&g_done[b], 1u);
        old = __shfl_sync(0xffffffffu, old, 0);
        if (old == 1u) {
            __threadfence();
            crf_combine(b, lane, out);
        }
    }
}

extern "C" void kernel_launch(void* const* d_in, const int* in_sizes, int n_in,
                              void* d_out, int out_size)
{
    const float* inputs = (const float*)d_in[0];
    const float* trans  = (const float*)d_in[1];
    const int*   tags   = (const int*)d_in[2];
    const int*   lens   = (const int*)d_in[3];
    float*       out    = (float*)d_out;

    crf_init_kernel<<<1, NJOBS>>>(lens);
    crf_half_kernel<<<148, 128>>>(inputs, trans, tags, lens, out);
}

// round 12
// speedup vs baseline: 1.7868x; 1.3389x over previous
#include <cuda_runtime.h>
#include <cstdint>

#define BB 512
#define TT 1024
#define NN 64
#define NJOBS (2 * BB)

// Bidirectional split of the CRF forward chain + LPT scheduling + fused
// combine. R12: x4-unrolled step blocks with renorm on every 4th step
// (exact power-of-2 renorm; bounds proven safe for N(0,1) inputs and
// 0.1*N(0,1) trans), int32 walking-pointer prefetch (no IMAD.WIDE, no
// predicates), block-ahead prefetch so tail steps use resident registers.
//   Forward  job: q_t = diag(exp x_t) * E^T q_{t-1},  t = 1..nf  (+ scores)
//   Backward job: r_{k-1} = E * (exp(x_k) . r_k),      k = L-1..nf+1
//   log_norm = C_f + C_b + log(q_nf . r_nf);  out = sc - log_norm

__device__ float          g_qf[BB][NN];
__device__ float          g_rb[BB][NN];
__device__ float          g_cf[BB];
__device__ float          g_cb[BB];
__device__ float          g_sc[BB];
__device__ unsigned       g_ctr;
__device__ unsigned       g_done[BB];
__device__ unsigned short g_order[NJOBS];

// ---- init: reset counters, rank jobs by length descending --------------
__global__ __launch_bounds__(NJOBS) void crf_init_kernel(
    const int* __restrict__ lens)
{
    __shared__ unsigned hist[513];
    __shared__ unsigned ofs[513];
    __shared__ unsigned scan[NJOBS];
    const int tid = threadIdx.x;

    if (tid == 0) g_ctr = 0u;
    if (tid < BB) g_done[tid] = 0u;
    if (tid < 513) { hist[tid] = 0u; ofs[tid] = 0u; }
    __syncthreads();

    const int b   = tid >> 1;
    const int dir = tid & 1;
    const int L   = lens[b];
    const int nf  = (L - 1) >> 1;
    const int len = dir ? (L - 1 - nf) : nf;   // 0..512
    atomicAdd(&hist[len], 1u);
    __syncthreads();

    scan[tid] = (tid <= 512) ? hist[512 - tid] : 0u;
    __syncthreads();
#pragma unroll
    for (int off = 1; off < NJOBS; off <<= 1) {
        unsigned v = (tid >= off) ? scan[tid - off] : 0u;
        __syncthreads();
        scan[tid] += v;
        __syncthreads();
    }

    const unsigned k     = (unsigned)(512 - len);
    const unsigned start = k ? scan[k - 1] : 0u;
    const unsigned pos   = start + atomicAdd(&ofs[len], 1u);
    g_order[pos] = (unsigned short)tid;
}

#define LOAD_CHUNK(dst, base)                                                 \
    do {                                                                      \
        asm volatile("ld.shared.v2.u64 {%0,%1}, [%2];"                        \
                     : "=l"(dst[0]), "=l"(dst[1]) : "r"(base));               \
        asm volatile("ld.shared.v2.u64 {%0,%1}, [%2];"                        \
                     : "=l"(dst[2]), "=l"(dst[3]) : "r"((base) + 16));        \
        asm volatile("ld.shared.v2.u64 {%0,%1}, [%2];"                        \
                     : "=l"(dst[4]), "=l"(dst[5]) : "r"((base) + 32));        \
        asm volatile("ld.shared.v2.u64 {%0,%1}, [%2];"                        \
                     : "=l"(dst[6]), "=l"(dst[7]) : "r"((base) + 48));        \
    } while (0)

#define FMA_CHUNK(g, vv)                                                      \
    do {                                                                      \
        _Pragma("unroll")                                                     \
        for (int k = 0; k < 8; k += 4) {                                      \
            asm("fma.rn.f32x2 %0, %1, %2, %0;" : "+l"(a0) : "l"(Ea[8*(g)+k])   , "l"(vv[k]));   \
            asm("fma.rn.f32x2 %0, %1, %2, %0;" : "+l"(b0) : "l"(Eb[8*(g)+k])   , "l"(vv[k]));   \
            asm("fma.rn.f32x2 %0, %1, %2, %0;" : "+l"(a1) : "l"(Ea[8*(g)+k+1]) , "l"(vv[k+1])); \
            asm("fma.rn.f32x2 %0, %1, %2, %0;" : "+l"(b1) : "l"(Eb[8*(g)+k+1]) , "l"(vv[k+1])); \
            asm("fma.rn.f32x2 %0, %1, %2, %0;" : "+l"(a2) : "l"(Ea[8*(g)+k+2]) , "l"(vv[k+2])); \
            asm("fma.rn.f32x2 %0, %1, %2, %0;" : "+l"(b2) : "l"(Eb[8*(g)+k+2]) , "l"(vv[k+2])); \
            asm("fma.rn.f32x2 %0, %1, %2, %0;" : "+l"(a3) : "l"(Ea[8*(g)+k+3]) , "l"(vv[k+3])); \
            asm("fma.rn.f32x2 %0, %1, %2, %0;" : "+l"(b3) : "l"(Eb[8*(g)+k+3]) , "l"(vv[k+3])); \
        }                                                                     \
    } while (0)

#define MATVEC_TAIL()                                                         \
    asm("add.rn.f32x2 %0, %0, %1;" : "+l"(a0) : "l"(a1));                     \
    asm("add.rn.f32x2 %0, %0, %1;" : "+l"(a2) : "l"(a3));                     \
    asm("add.rn.f32x2 %0, %0, %1;" : "+l"(b0) : "l"(b1));                     \
    asm("add.rn.f32x2 %0, %0, %1;" : "+l"(b2) : "l"(b3));                     \
    asm("add.rn.f32x2 %0, %0, %1;" : "+l"(a0) : "l"(a2));                     \
    asm("add.rn.f32x2 %0, %0, %1;" : "+l"(b0) : "l"(b2));                     \
    asm("mov.b64 {%0,%1}, %2;" : "=f"(gal), "=f"(gah) : "l"(a0));             \
    asm("mov.b64 {%0,%1}, %2;" : "=f"(gbl), "=f"(gbh) : "l"(b0));

#define MATVEC_NR(sbase)                                                      \
    unsigned long long v0[8], v1[8];                                          \
    LOAD_CHUNK(v0, sbase);                                                    \
    LOAD_CHUNK(v1, (sbase) + 64);                                             \
    unsigned long long a0 = 0ull, a1 = 0ull, a2 = 0ull, a3 = 0ull;            \
    unsigned long long b0 = 0ull, b1 = 0ull, b2 = 0ull, b3 = 0ull;            \
    float gal, gah, gbl, gbh;                                                 \
    FMA_CHUNK(0, v0);                                                         \
    LOAD_CHUNK(v0, (sbase) + 128);                                            \
    FMA_CHUNK(1, v1);                                                         \
    LOAD_CHUNK(v1, (sbase) + 192);                                            \
    FMA_CHUNK(2, v0);                                                         \
    FMA_CHUNK(3, v1);                                                         \
    MATVEC_TAIL()

#define MATVEC_RN(sbase)                                                      \
    unsigned long long v0[8], v1[8];                                          \
    LOAD_CHUNK(v0, sbase);                                                    \
    LOAD_CHUNK(v1, (sbase) + 64);                                             \
    unsigned q0bits;                                                          \
    asm("mov.b64 {%0,_}, %1;" : "=r"(q0bits) : "l"(v0[0]));                   \
    const int e = (int)((q0bits >> 23) & 0xff) - 127;                         \
    Ce += e;                                                                  \
    const float scale = __uint_as_float((unsigned)(127 - e) << 23);           \
    unsigned long long a0 = 0ull, a1 = 0ull, a2 = 0ull, a3 = 0ull;            \
    unsigned long long b0 = 0ull, b1 = 0ull, b2 = 0ull, b3 = 0ull;            \
    float gal, gah, gbl, gbh;                                                 \
    FMA_CHUNK(0, v0);                                                         \
    LOAD_CHUNK(v0, (sbase) + 128);                                            \
    FMA_CHUNK(1, v1);                                                         \
    LOAD_CHUNK(v1, (sbase) + 192);                                            \
    FMA_CHUNK(2, v0);                                                         \
    FMA_CHUNK(3, v1);                                                         \
    MATVEC_TAIL()

#define STS64P(addr, lo, hi)                                                  \
    do {                                                                      \
        unsigned long long _pk;                                               \
        asm("mov.b64 %0, {%1,%2};" : "=l"(_pk) : "f"(lo), "f"(hi));           \
        asm volatile("st.shared.b64 [%0], %1;" :: "r"(addr), "l"(_pk)         \
                     : "memory");                                             \
    } while (0)

// forward step bodies
#define FSTEP_NR(xva, xvb)                                                    \
    do {                                                                      \
        const float sxa = __expf(xva);                                        \
        const float sxb = __expf(xvb);                                        \
        MATVEC_NR(sw0);                                                       \
        qa = (gal + gah) * sxa;                                               \
        qb = (gbl + gbh) * sxb;                                               \
        STS64P(sst, qa, qb);                                                  \
    } while (0)

#define FSTEP_RN(xva, xvb)                                                    \
    do {                                                                      \
        const float sxa = __expf(xva);                                        \
        const float sxb = __expf(xvb);                                        \
        MATVEC_RN(sw0);                                                       \
        qa = (gal + gah) * (sxa * scale);                                     \
        qb = (gbl + gbh) * (sxb * scale);                                     \
        STS64P(sst, qa, qb);                                                  \
    } while (0)

// backward step bodies
#define BSTEP_NR(xva, xvb)                                                    \
    do {                                                                      \
        const float ua = __expf(xva) * ra;                                    \
        const float ub = __expf(xvb) * rb;                                    \
        STS64P(sst, ua, ub);                                                  \
        MATVEC_NR(sw0);                                                       \
        ra = gal + gah;                                                       \
        rb = gbl + gbh;                                                       \
    } while (0)

#define BSTEP_RN(xva, xvb)                                                    \
    do {                                                                      \
        const float ua = __expf(xva) * ra;                                    \
        const float ub = __expf(xvb) * rb;                                    \
        STS64P(sst, ua, ub);                                                  \
        MATVEC_RN(sw0);                                                       \
        ra = (gal + gah) * scale;                                             \
        rb = (gbl + gbh) * scale;                                             \
    } while (0)

__device__ __forceinline__ void crf_combine(int b, int lane,
                                            float* __restrict__ out)
{
    const float d0 = __ldcg(&g_qf[b][lane])      * __ldcg(&g_rb[b][lane]);
    const float d1 = __ldcg(&g_qf[b][lane + 32]) * __ldcg(&g_rb[b][lane + 32]);
    float d = d0 + d1;
#pragma unroll
    for (int o = 16; o; o >>= 1) d += __shfl_xor_sync(0xffffffffu, d, o);
    if (lane == 0) {
        const float log_norm = __ldcg(&g_cf[b]) + __ldcg(&g_cb[b]) + __logf(d);
        out[b] = __ldcg(&g_sc[b]) - log_norm;
    }
}

__global__ __launch_bounds__(128, 1) void crf_half_kernel(
    const float* __restrict__ inputs,   // [B, T, N]
    const float* __restrict__ trans,    // [N, N]
    const int*   __restrict__ tags,     // [B, T]
    const int*   __restrict__ lens,     // [B]
    float*       __restrict__ out)      // [B]
{
    const int lane = threadIdx.x & 31;
    const int wid  = threadIdx.x >> 5;

    __shared__ __align__(16) float pbuf[4][NN];

    for (;;) {
        unsigned j;
        if (lane == 0) j = atomicAdd(&g_ctr, 1u);
        j = __shfl_sync(0xffffffffu, j, 0);
        if (j >= NJOBS) return;
        j = g_order[j];                      // LPT order

        const int b   = (int)(j >> 1);
        const int dir = (int)(j & 1);
        const int L   = lens[b];
        const int nf  = (L - 1) >> 1;
        const size_t tbase = (size_t)b * TT;
        const float* xp = inputs + tbase * NN;

        const unsigned sw0 =
            (unsigned)__cvta_generic_to_shared(&pbuf[wid][0]);
        const unsigned sst = sw0 + (unsigned)(lane * 8);

        if (dir == 0) {
            // ---------------- FORWARD half + scores ----------------------
            float sc = 0.f;
            for (int t = lane; t < L; t += 32) {
                int tg = tags[tbase + t];
                sc += inputs[(tbase + t) * NN + tg];
                if (t >= 1) {
                    int tp = tags[tbase + t - 1];
                    sc += trans[tp * NN + tg];
                }
            }
#pragma unroll
            for (int o = 16; o; o >>= 1)
                sc += __shfl_xor_sync(0xffffffffu, sc, o);

            // E = exp(trans), interleaved row packing:
            // Ea[w] = (E[w][lane], E[w+32][lane]) matches p word w.
            unsigned long long Ea[32], Eb[32];
#pragma unroll
            for (int w = 0; w < 32; ++w) {
                float e0 = __expf(trans[w * NN + lane]);
                float e1 = __expf(trans[(w + 32) * NN + lane]);
                asm("mov.b64 %0, {%1,%2};" : "=l"(Ea[w]) : "f"(e0), "f"(e1));
                float f0 = __expf(trans[w * NN + lane + 32]);
                float f1 = __expf(trans[(w + 32) * NN + lane + 32]);
                asm("mov.b64 %0, {%1,%2};" : "=l"(Eb[w]) : "f"(f0), "f"(f1));
            }

            float x0a = xp[lane];
            float x0b = xp[lane + 32];
            float M0  = __shfl_sync(0xffffffffu, x0a, 0);
            float qa  = __expf(x0a - M0);
            float qb  = __expf(x0b - M0);
            STS64P(sst, qa, qb);

            int Ce = 0;

            // preload x for t = 1..4 (always in-bounds: rows <= 4 < TT)
            const float* xq = xp + NN;
            float xa0 = xq[lane],          xb0 = xq[lane + 32];
            float xa1 = xq[NN + lane],     xb1 = xq[NN + lane + 32];
            float xa2 = xq[2 * NN + lane], xb2 = xq[2 * NN + lane + 32];
            float xa3 = xq[3 * NN + lane], xb3 = xq[3 * NN + lane + 32];
            const float* xf = xp + 5 * NN;   // block-ahead pointer (t+4..)

            int t = 1;
            for (; t + 3 <= nf; t += 4) {
                // prefetch next block (rows t+4..t+7; <= 515 < TT, in-bounds)
                const float ya0 = xf[lane],          yb0 = xf[lane + 32];
                const float ya1 = xf[NN + lane],     yb1 = xf[NN + lane + 32];
                const float ya2 = xf[2 * NN + lane], yb2 = xf[2 * NN + lane + 32];
                const float ya3 = xf[3 * NN + lane], yb3 = xf[3 * NN + lane + 32];

                FSTEP_NR(xa0, xb0);
                FSTEP_NR(xa1, xb1);
                FSTEP_NR(xa2, xb2);
                FSTEP_RN(xa3, xb3);

                xa0 = ya0; xb0 = yb0; xa1 = ya1; xb1 = yb1;
                xa2 = ya2; xb2 = yb2; xa3 = ya3; xb3 = yb3;
                xf += 4 * NN;
            }
            // tail (<=3 steps), x already resident
            if (t     <= nf) { FSTEP_RN(xa0, xb0); }
            if (t + 1 <= nf) { FSTEP_RN(xa1, xb1); }
            if (t + 2 <= nf) { FSTEP_RN(xa2, xb2); }

            g_qf[b][lane]      = qa;
            g_qf[b][lane + 32] = qb;
            if (lane == 0) {
                g_cf[b] = M0 + (float)Ce * 0.6931471805599453f;
                g_sc[b] = sc;
            }
        } else {
            // ---------------- BACKWARD half ------------------------------
            // Ea[w] = (E[lane][w], E[lane][w+32]) matches u word w.
            unsigned long long Ea[32], Eb[32];
#pragma unroll
            for (int w = 0; w < 32; ++w) {
                float e0 = __expf(trans[lane * NN + w]);
                float e1 = __expf(trans[lane * NN + w + 32]);
                asm("mov.b64 %0, {%1,%2};" : "=l"(Ea[w]) : "f"(e0), "f"(e1));
                float f0 = __expf(trans[(lane + 32) * NN + w]);
                float f1 = __expf(trans[(lane + 32) * NN + w + 32]);
                asm("mov.b64 %0, {%1,%2};" : "=l"(Eb[w]) : "f"(f0), "f"(f1));
            }

            const int nb = (L - 1) - nf;
            float ra = 1.f, rb = 1.f;
            int Ce = 0;

            // preload x for s = 0..3 (rows L-1-u, clamped >= 0)
            int k0 = L - 1;
            {
                const int c0 = k0 > 0 ? k0 : 0;
                const int c1 = k0 - 1 > 0 ? k0 - 1 : 0;
                const int c2 = k0 - 2 > 0 ? k0 - 2 : 0;
                const int c3 = k0 - 3 > 0 ? k0 - 3 : 0;
                (void)c0;
                // fallthrough loads below
                // (indices multiplied once; int32 math)
                // rows:
                // xa0 = row k0, xa1 = row k0-1, ...
                // clamped so b==0 short jobs stay in-bounds
                // (values unused when s >= nb)
                // NOLINT
                ;
            }
            const int r0 = (L - 1)     > 0 ? (L - 1)     : 0;
            const int r1 = (L - 2)     > 0 ? (L - 2)     : 0;
            const int r2 = (L - 3)     > 0 ? (L - 3)     : 0;
            const int r3 = (L - 4)     > 0 ? (L - 4)     : 0;
            float xa0 = xp[r0 * NN + lane], xb0 = xp[r0 * NN + lane + 32];
            float xa1 = xp[r1 * NN + lane], xb1 = xp[r1 * NN + lane + 32];
            float xa2 = xp[r2 * NN + lane], xb2 = xp[r2 * NN + lane + 32];
            float xa3 = xp[r3 * NN + lane], xb3 = xp[r3 * NN + lane + 32];

            int kk = L - 5;   // row of next block's first prefetch
            int s = 0;
            for (; s + 3 < nb; s += 4) {
                const int c0 = kk     > 0 ? kk     : 0;
                const int c1 = kk - 1 > 0 ? kk - 1 : 0;
                const int c2 = kk - 2 > 0 ? kk - 2 : 0;
                const int c3 = kk - 3 > 0 ? kk - 3 : 0;
                const float ya0 = xp[c0 * NN + lane], yb0 = xp[c0 * NN + lane + 32];
                const float ya1 = xp[c1 * NN + lane], yb1 = xp[c1 * NN + lane + 32];
                const float ya2 = xp[c2 * NN + lane], yb2 = xp[c2 * NN + lane + 32];
                const float ya3 = xp[c3 * NN + lane], yb3 = xp[c3 * NN + lane + 32];

                BSTEP_NR(xa0, xb0);
                BSTEP_NR(xa1, xb1);
                BSTEP_NR(xa2, xb2);
                BSTEP_RN(xa3, xb3);

                xa0 = ya0; xb0 = yb0; xa1 = ya1; xb1 = yb1;
                xa2 = ya2; xb2 = yb2; xa3 = ya3; xb3 = yb3;
                kk -= 4;
            }
            // tail (<=3 steps), x already resident
            if (s     < nb) { BSTEP_RN(xa0, xb0); }
            if (s + 1 < nb) { BSTEP_RN(xa1, xb1); }
            if (s + 2 < nb) { BSTEP_RN(xa2, xb2); }

            g_rb[b][lane]      = ra;
            g_rb[b][lane + 32] = rb;
            if (lane == 0)
                g_cb[b] = (float)Ce * 0.6931471805599453f;
        }

        // ---- completion: second finisher combines ----
        __threadfence();
        unsigned old = 0;
        if (lane == 0) old = atomicAdd(&g_done[b], 1u);
        old = __shfl_sync(0xffffffffu, old, 0);
        if (old == 1u) {
            __threadfence();
            crf_combine(b, lane, out);
        }
    }
}

extern "C" void kernel_launch(void* const* d_in, const int* in_sizes, int n_in,
                              void* d_out, int out_size)
{
    const float* inputs = (const float*)d_in[0];
    const float* trans  = (const float*)d_in[1];
    const int*   tags   = (const int*)d_in[2];
    const int*   lens   = (const int*)d_in[3];
    float*       out    = (float*)d_out;

    crf_init_kernel<<<1, NJOBS>>>(lens);
    crf_half_kernel<<<148, 128>>>(inputs, trans, tags, lens, out);
}